// round 1
// baseline (speedup 1.0000x reference)
#include <cuda_runtime.h>
#include <math.h>

#define BATCH 2048
#define INPUT_DIM 256
#define UNITS 1024
#define STEPS 96
#define OUTU 256
#define GATES 4096            // 4*UNITS
#define NCOMB (GATES + OUTU)  // 4352 : [Wc | Wd] combined columns

// Scratch (device globals: no allocation allowed in kernel_launch)
__device__ float g_Wcd[UNITS * NCOMB];   // combined recurrent+output weights [1024, 4352]
__device__ float g_bcd[NCOMB];           // combined bias
__device__ float g_z[BATCH * GATES];     // gate pre-activations [2048, 4096]
__device__ float g_h[BATCH * UNITS];     // hidden state
__device__ float g_c[BATCH * UNITS];     // cell state

// ---------------------------------------------------------------------------
// bcd[0:4096] = b + bd @ Wk ;  bcd[4096:4352] = bd
// ---------------------------------------------------------------------------
__global__ void bias_combine(const float* __restrict__ b,
                             const float* __restrict__ bd,
                             const float* __restrict__ Wk) {
    int j = blockIdx.x * blockDim.x + threadIdx.x;
    if (j < GATES) {
        float s = b[j];
        #pragma unroll 4
        for (int k = 0; k < INPUT_DIM; ++k)
            s += bd[k] * Wk[(size_t)k * GATES + j];
        g_bcd[j] = s;
    } else if (j < NCOMB) {
        g_bcd[j] = bd[j - GATES];
    }
}

// Copy Wd into the last 256 columns of g_Wcd
__global__ void copy_wd(const float* __restrict__ Wd) {
    int idx = blockIdx.x * blockDim.x + threadIdx.x;
    if (idx < UNITS * OUTU) {
        int r = idx / OUTU, c = idx % OUTU;
        g_Wcd[(size_t)r * NCOMB + GATES + c] = Wd[idx];
    }
}

// ---------------------------------------------------------------------------
// Pointwise LSTM update: reads g_z (2048x4096, gate order i,f,g,o), updates
// g_h / g_c in place.
// ---------------------------------------------------------------------------
__global__ void lstm_pointwise() {
    int idx = blockIdx.x * blockDim.x + threadIdx.x;
    if (idx >= BATCH * UNITS) return;
    int bi = idx >> 10;      // /1024
    int u  = idx & 1023;
    const float* zr = g_z + (size_t)bi * GATES;
    float zi = zr[u];
    float zf = zr[UNITS + u];
    float zg = zr[2 * UNITS + u];
    float zo = zr[3 * UNITS + u];
    float ig = 1.0f / (1.0f + expf(-zi));
    float fg = 1.0f / (1.0f + expf(-zf));
    float og = 1.0f / (1.0f + expf(-zo));
    float cn = fg * g_c[idx] + ig * tanhf(zg);
    g_c[idx] = cn;
    g_h[idx] = og * tanhf(cn);
}

// ---------------------------------------------------------------------------
// Generic fp32 tiled GEMM, 128x128 block tile, BK=8, 256 threads, 8x8/thread.
//   C(logical) = A[M,K]@B[K,N] (+ A2[M,K2]@B2[K2,N]) (+ bias[n]) (+ Cadd[m,n])
// Output split: block columns with global col >= nsplit are routed to
//   C2 + c2off + m*ldc2 + (col - nsplit)   (used to write preds into d_out).
// All dims must be multiples of the tile sizes (they are, by construction).
// ---------------------------------------------------------------------------
__global__ __launch_bounds__(256)
void sgemm128(const float* __restrict__ A, int lda,
              const float* __restrict__ B, int ldb, int K,
              const float* __restrict__ A2, int lda2,
              const float* __restrict__ B2, int ldb2, int K2,
              const float* __restrict__ bias,
              const float* __restrict__ Cadd, int ldadd,
              float* __restrict__ C, int ldc,
              int nsplit, float* __restrict__ C2, int ldc2, int c2off) {
    __shared__ float As[8][128];
    __shared__ float Bs[8][128];

    const int tid = threadIdx.x;
    const int tx = tid & 15;       // 0..15
    const int ty = tid >> 4;       // 0..15
    const int row0 = blockIdx.y * 128;
    const int col0 = blockIdx.x * 128;

    float acc[8][8];
    #pragma unroll
    for (int i = 0; i < 8; ++i)
        #pragma unroll
        for (int j = 0; j < 8; ++j) acc[i][j] = 0.0f;

    const int arow = tid >> 1;         // 0..127
    const int acol = (tid & 1) << 2;   // 0 or 4
    const int brow = tid >> 5;         // 0..7
    const int bcol = (tid & 31) << 2;  // 0..124

    #pragma unroll 1
    for (int pass = 0; pass < 2; ++pass) {
        const float* Ap  = pass ? A2 : A;
        const float* Bp  = pass ? B2 : B;
        const int    Kp  = pass ? K2 : K;
        const int    ldA = pass ? lda2 : lda;
        const int    ldB = pass ? ldb2 : ldb;
        if (Kp == 0) continue;
        const float* Arow = Ap + (size_t)(row0 + arow) * ldA + acol;
        const float* Brow = Bp + (size_t)brow * ldB + col0 + bcol;
        for (int k0 = 0; k0 < Kp; k0 += 8) {
            float4 av = *reinterpret_cast<const float4*>(Arow + k0);
            float4 bv = *reinterpret_cast<const float4*>(Brow + (size_t)k0 * ldB);
            As[acol + 0][arow] = av.x;
            As[acol + 1][arow] = av.y;
            As[acol + 2][arow] = av.z;
            As[acol + 3][arow] = av.w;
            *reinterpret_cast<float4*>(&Bs[brow][bcol]) = bv;
            __syncthreads();
            #pragma unroll
            for (int k = 0; k < 8; ++k) {
                float a[8], bb[8];
                #pragma unroll
                for (int i = 0; i < 8; ++i) a[i] = As[k][ty * 8 + i];
                #pragma unroll
                for (int j = 0; j < 8; ++j) bb[j] = Bs[k][tx * 8 + j];
                #pragma unroll
                for (int i = 0; i < 8; ++i)
                    #pragma unroll
                    for (int j = 0; j < 8; ++j)
                        acc[i][j] = fmaf(a[i], bb[j], acc[i][j]);
            }
            __syncthreads();
        }
    }

    // Epilogue (tile is entirely on one side of nsplit: nsplit % 128 == 0)
    const int gcol = col0 + tx * 8;
    float* Co; int ld; int ocol;
    if (C2 != nullptr && gcol >= nsplit) {
        Co = C2 + c2off; ld = ldc2; ocol = gcol - nsplit;
    } else {
        Co = C; ld = ldc; ocol = gcol;
    }
    #pragma unroll
    for (int i = 0; i < 8; ++i) {
        int r = row0 + ty * 8 + i;
        #pragma unroll
        for (int j = 0; j < 8; j += 4) {
            float4 v = make_float4(acc[i][j], acc[i][j + 1], acc[i][j + 2], acc[i][j + 3]);
            if (bias) {
                v.x += bias[gcol + j];
                v.y += bias[gcol + j + 1];
                v.z += bias[gcol + j + 2];
                v.w += bias[gcol + j + 3];
            }
            if (Cadd) {
                float4 a4 = *reinterpret_cast<const float4*>(Cadd + (size_t)r * ldadd + gcol + j);
                v.x += a4.x; v.y += a4.y; v.z += a4.z; v.w += a4.w;
            }
            *reinterpret_cast<float4*>(Co + (size_t)r * ld + ocol + j) = v;
        }
    }
}

// ---------------------------------------------------------------------------
extern "C" void kernel_launch(void* const* d_in, const int* in_sizes, int n_in,
                              void* d_out, int out_size) {
    const float* x0 = (const float*)d_in[0];  // last_input [2048,256]
    const float* h0 = (const float*)d_in[1];  // [2048,1024]
    const float* c0 = (const float*)d_in[2];  // [2048,1024]
    const float* Wk = (const float*)d_in[3];  // [256,4096]
    const float* Wr = (const float*)d_in[4];  // [1024,4096]
    const float* b  = (const float*)d_in[5];  // [4096]
    const float* Wd = (const float*)d_in[6];  // [1024,256]
    const float* bd = (const float*)d_in[7];  // [256]
    float* out = (float*)d_out;               // [2048, 96, 256]

    float *pWcd, *pBcd, *pZ, *pH, *pC;
    cudaGetSymbolAddress((void**)&pWcd, g_Wcd);
    cudaGetSymbolAddress((void**)&pBcd, g_bcd);
    cudaGetSymbolAddress((void**)&pZ,   g_z);
    cudaGetSymbolAddress((void**)&pH,   g_h);
    cudaGetSymbolAddress((void**)&pC,   g_c);

    const int BIG = 1 << 30;
    const int ldo = STEPS * OUTU;  // 24576, d_out row stride per batch

    // State init
    cudaMemcpyAsync(pH, h0, (size_t)BATCH * UNITS * sizeof(float),
                    cudaMemcpyDeviceToDevice, 0);
    cudaMemcpyAsync(pC, c0, (size_t)BATCH * UNITS * sizeof(float),
                    cudaMemcpyDeviceToDevice, 0);

    // Precompute combined weights / bias:
    //   g_Wcd[:, 0:4096]   = Wd @ Wk + Wr
    //   g_Wcd[:, 4096:]    = Wd
    //   g_bcd[0:4096]      = b + bd @ Wk ; g_bcd[4096:] = bd
    bias_combine<<<(NCOMB + 255) / 256, 256>>>(b, bd, Wk);
    copy_wd<<<(UNITS * OUTU + 255) / 256, 256>>>(Wd);
    sgemm128<<<dim3(GATES / 128, UNITS / 128), 256>>>(
        Wd, OUTU, Wk, GATES, INPUT_DIM,
        nullptr, 0, nullptr, 0, 0,
        nullptr, Wr, GATES,
        pWcd, NCOMB, BIG, nullptr, 0, 0);

    // Step 0: z = x0 @ Wk + h0 @ Wr + b   (dual-K GEMM)
    sgemm128<<<dim3(GATES / 128, BATCH / 128), 256>>>(
        x0, INPUT_DIM, Wk, GATES, INPUT_DIM,
        h0, UNITS, Wr, GATES, UNITS,
        b, nullptr, 0,
        pZ, GATES, BIG, nullptr, 0, 0);
    lstm_pointwise<<<(BATCH * UNITS) / 256, 256>>>();

    // Steps 1..95: z_t | pred_{t-1} = h_t @ [Wc | Wd] + [bc | bd]
    for (int t = 1; t < STEPS; ++t) {
        sgemm128<<<dim3(NCOMB / 128, BATCH / 128), 256>>>(
            pH, UNITS, pWcd, NCOMB, UNITS,
            nullptr, 0, nullptr, 0, 0,
            pBcd, nullptr, 0,
            pZ, GATES,                 // cols [0,4096) -> gate preacts
            GATES, out, ldo, (t - 1) * OUTU);  // cols [4096,4352) -> pred_{t-1}
        lstm_pointwise<<<(BATCH * UNITS) / 256, 256>>>();
    }

    // Final prediction: pred_95 = h_96 @ Wd + bd
    sgemm128<<<dim3(OUTU / 128, BATCH / 128), 256>>>(
        pH, UNITS, Wd, OUTU, UNITS,
        nullptr, 0, nullptr, 0, 0,
        bd, nullptr, 0,
        out + (STEPS - 1) * OUTU, ldo, BIG, nullptr, 0, 0);
}

// round 3
// speedup vs baseline: 1.7859x; 1.7859x over previous
#include <cuda_runtime.h>
#include <cuda_bf16.h>
#include <cstdint>
#include <math.h>

#define BATCH 2048
#define UNITS 1024
#define GATES 4096
#define OUTU 256
#define NCOMB 4352            // [Wc | Wd]
#define STEPS 96
#define K0 1280               // step-0 K: [x | h]
#define LDO (STEPS * OUTU)

// ------------------------------ device scratch ------------------------------
__device__ __align__(256) float g_Wcd[UNITS * NCOMB];   // fp32 combined weights
__device__ __align__(256) float g_bcd[NCOMB];           // combined bias
__device__ __align__(256) float g_z[BATCH * GATES];     // gate preacts
__device__ __align__(256) float g_c[BATCH * UNITS];     // cell state fp32
__device__ __align__(256) __nv_bfloat16 g_hhi[BATCH * UNITS];
__device__ __align__(256) __nv_bfloat16 g_hlo[BATCH * UNITS];
__device__ __align__(256) __nv_bfloat16 g_wthi[(size_t)NCOMB * UNITS];  // W^T [4352][1024]
__device__ __align__(256) __nv_bfloat16 g_wtlo[(size_t)NCOMB * UNITS];
__device__ __align__(256) __nv_bfloat16 g_w0hi[(size_t)GATES * K0];     // step0 W^T [4096][1280]
__device__ __align__(256) __nv_bfloat16 g_w0lo[(size_t)GATES * K0];
__device__ __align__(256) __nv_bfloat16 g_a0hi[(size_t)BATCH * K0];     // step0 A=[x|h]
__device__ __align__(256) __nv_bfloat16 g_a0lo[(size_t)BATCH * K0];

// ------------------------------ PTX helpers ---------------------------------
__device__ __forceinline__ uint32_t smem_u32(const void* p) {
    uint32_t a;
    asm("{ .reg .u64 t; cvta.to.shared.u64 t, %1; cvt.u32.u64 %0, t; }" : "=r"(a) : "l"(p));
    return a;
}
__device__ __forceinline__ uint32_t swz(uint32_t off) {       // SW128 swizzle
    return off ^ ((off >> 3) & 0x70);
}
__device__ __forceinline__ void cpa16(uint32_t dst, const void* src) {
    asm volatile("cp.async.cg.shared.global [%0], [%1], 16;" :: "r"(dst), "l"(src) : "memory");
}
#define CP_COMMIT()  asm volatile("cp.async.commit_group;" ::: "memory")
#define CP_WAIT(n)   asm volatile("cp.async.wait_group %0;" :: "n"(n) : "memory")

__device__ __forceinline__ void ldsm4(uint32_t* r, uint32_t addr) {
    asm volatile("ldmatrix.sync.aligned.m8n8.x4.shared.b16 {%0,%1,%2,%3}, [%4];"
        : "=r"(r[0]), "=r"(r[1]), "=r"(r[2]), "=r"(r[3]) : "r"(addr));
}
__device__ __forceinline__ void mma16816(float* d, const uint32_t* a,
                                         uint32_t b0, uint32_t b1) {
    asm volatile("mma.sync.aligned.m16n8k16.row.col.f32.bf16.bf16.f32 "
        "{%0,%1,%2,%3}, {%4,%5,%6,%7}, {%8,%9}, {%0,%1,%2,%3};"
        : "+f"(d[0]), "+f"(d[1]), "+f"(d[2]), "+f"(d[3])
        : "r"(a[0]), "r"(a[1]), "r"(a[2]), "r"(a[3]), "r"(b0), "r"(b1));
}

// ------------------------------ bf16-split HMMA GEMM -------------------------
// C[2048 x Ncols] = A[2048 x K] @ B^T, A [M][K] row-major hi/lo, B [N][K] hi/lo.
// Block tile 128x128, K-chunk 64, 3-stage cp.async pipeline, 8 warps (32x64 each).
// acc = Ahi*Bhi + Ahi*Blo + Alo*Bhi  (lo*lo dropped, ~2^-16 relative)
#define KC 64
#define OFF_AHI 0
#define OFF_ALO 16384
#define OFF_BHI 32768
#define OFF_BLO 49152
#define STAGE_BYTES 65536
#define SMEM_TOTAL (3 * STAGE_BYTES)

__device__ __forceinline__ void load_chunk(
    uint32_t sb, int tid,
    const __nv_bfloat16* __restrict__ ahi, const __nv_bfloat16* __restrict__ alo,
    const __nv_bfloat16* __restrict__ bhi, const __nv_bfloat16* __restrict__ blo,
    int r0, int n0, int K, int kc)
{
    const int kcol = kc * KC;
    #pragma unroll
    for (int i = 0; i < 4; ++i) {
        int q = tid + i * 256;
        int row = q >> 3, jj = q & 7;              // 128 rows x 8 chunks of 16B
        uint32_t so = swz(row * 128 + jj * 16);
        size_t ga = (size_t)(r0 + row) * K + kcol + jj * 8;
        size_t gb = (size_t)(n0 + row) * K + kcol + jj * 8;
        cpa16(sb + OFF_AHI + so, ahi + ga);
        cpa16(sb + OFF_ALO + so, alo + ga);
        cpa16(sb + OFF_BHI + so, bhi + gb);
        cpa16(sb + OFF_BLO + so, blo + gb);
    }
    CP_COMMIT();
}

__global__ __launch_bounds__(256, 1)
void bgemm(const __nv_bfloat16* __restrict__ ahi, const __nv_bfloat16* __restrict__ alo,
           const __nv_bfloat16* __restrict__ bhi, const __nv_bfloat16* __restrict__ blo,
           int K, const float* __restrict__ bias, int n_tile_off, int t,
           float* __restrict__ outp)
{
    extern __shared__ __align__(1024) char smem[];
    const uint32_t sbase = smem_u32(smem);
    const int tid = threadIdx.x;
    const int lane = tid & 31, w = tid >> 5;
    const int wm = w & 3, wn = w >> 2;             // warp grid 4 (m) x 2 (n)
    const int r0 = blockIdx.y * 128;
    const int n0 = (blockIdx.x + n_tile_off) * 128;
    const int nch = K / KC;

    float d[2][8][4];
    #pragma unroll
    for (int mi = 0; mi < 2; ++mi)
        #pragma unroll
        for (int nj = 0; nj < 8; ++nj)
            #pragma unroll
            for (int q = 0; q < 4; ++q) d[mi][nj][q] = 0.0f;

    load_chunk(sbase + 0 * STAGE_BYTES, tid, ahi, alo, bhi, blo, r0, n0, K, 0);
    load_chunk(sbase + 1 * STAGE_BYTES, tid, ahi, alo, bhi, blo, r0, n0, K, 1);

    const int lr = lane & 7, sel = lane >> 3;

    for (int kc = 0; kc < nch; ++kc) {
        if (kc + 2 < nch) {
            load_chunk(sbase + ((kc + 2) % 3) * STAGE_BYTES, tid,
                       ahi, alo, bhi, blo, r0, n0, K, kc + 2);
            CP_WAIT(2);
        } else if (kc + 1 < nch) {
            CP_WAIT(1);
        } else {
            CP_WAIT(0);
        }
        __syncthreads();
        const uint32_t sb = sbase + (kc % 3) * STAGE_BYTES;

        #pragma unroll
        for (int k16 = 0; k16 < 4; ++k16) {
            uint32_t ah[2][4], al[2][4];
            #pragma unroll
            for (int mi = 0; mi < 2; ++mi) {
                int row = wm * 32 + mi * 16 + lr + (sel & 1) * 8;
                int kb = (k16 * 16 + (sel >> 1) * 8) * 2;
                uint32_t off = swz(row * 128 + kb);
                ldsm4(ah[mi], sb + OFF_AHI + off);
                ldsm4(al[mi], sb + OFF_ALO + off);
            }
            uint32_t bh[4][4], bl[4][4];
            #pragma unroll
            for (int njp = 0; njp < 4; ++njp) {
                int nrow = wn * 64 + njp * 16 + lr + (sel >> 1) * 8;
                int kb = (k16 * 16 + (sel & 1) * 8) * 2;
                uint32_t off = swz(nrow * 128 + kb);
                ldsm4(bh[njp], sb + OFF_BHI + off);
                ldsm4(bl[njp], sb + OFF_BLO + off);
            }
            #pragma unroll
            for (int mi = 0; mi < 2; ++mi)
                #pragma unroll
                for (int nj = 0; nj < 8; ++nj) {
                    uint32_t b0h = bh[nj >> 1][(nj & 1) * 2];
                    uint32_t b1h = bh[nj >> 1][(nj & 1) * 2 + 1];
                    uint32_t b0l = bl[nj >> 1][(nj & 1) * 2];
                    uint32_t b1l = bl[nj >> 1][(nj & 1) * 2 + 1];
                    mma16816(d[mi][nj], ah[mi], b0h, b1h);
                    mma16816(d[mi][nj], ah[mi], b0l, b1l);
                    mma16816(d[mi][nj], al[mi], b0h, b1h);
                }
        }
        __syncthreads();
    }

    // epilogue: c frag rows t/4 (+8), cols 2*(t%4)
    const bool isPred = (n0 >= GATES);
    const int qr = lane >> 2, qc = (lane & 3) * 2;
    #pragma unroll
    for (int mi = 0; mi < 2; ++mi) {
        #pragma unroll
        for (int half = 0; half < 2; ++half) {
            int r = r0 + wm * 32 + mi * 16 + qr + half * 8;
            float* rowp = isPred
                ? (outp + (size_t)r * LDO + (size_t)(t - 1) * OUTU + (n0 - GATES))
                : (g_z + (size_t)r * GATES + n0);
            #pragma unroll
            for (int nj = 0; nj < 8; ++nj) {
                int c = wn * 64 + nj * 8 + qc;
                float2 v;
                v.x = d[mi][nj][half * 2 + 0] + bias[n0 + c];
                v.y = d[mi][nj][half * 2 + 1] + bias[n0 + c + 1];
                *reinterpret_cast<float2*>(rowp + c) = v;
            }
        }
    }
}

// ------------------------------ pointwise LSTM -------------------------------
__global__ void lstm_pointwise() {
    int idx = blockIdx.x * blockDim.x + threadIdx.x;
    if (idx >= BATCH * UNITS / 4) return;
    int r = idx >> 8;
    int u = (idx & 255) << 2;
    const float* zr = g_z + (size_t)r * GATES;
    float4 zi = *reinterpret_cast<const float4*>(zr + u);
    float4 zf = *reinterpret_cast<const float4*>(zr + UNITS + u);
    float4 zg = *reinterpret_cast<const float4*>(zr + 2 * UNITS + u);
    float4 zo = *reinterpret_cast<const float4*>(zr + 3 * UNITS + u);
    size_t coff = (size_t)r * UNITS + u;
    float4 c = *reinterpret_cast<float4*>(g_c + coff);

    float zis[4] = {zi.x, zi.y, zi.z, zi.w};
    float zfs[4] = {zf.x, zf.y, zf.z, zf.w};
    float zgs[4] = {zg.x, zg.y, zg.z, zg.w};
    float zos[4] = {zo.x, zo.y, zo.z, zo.w};
    float cs[4] = {c.x, c.y, c.z, c.w};
    float hs[4];
    #pragma unroll
    for (int k = 0; k < 4; ++k) {
        float ig = 1.0f / (1.0f + expf(-zis[k]));
        float fg = 1.0f / (1.0f + expf(-zfs[k]));
        float og = 1.0f / (1.0f + expf(-zos[k]));
        float cn = fg * cs[k] + ig * tanhf(zgs[k]);
        cs[k] = cn;
        hs[k] = og * tanhf(cn);
    }
    *reinterpret_cast<float4*>(g_c + coff) = make_float4(cs[0], cs[1], cs[2], cs[3]);

    __nv_bfloat16 hi[4], lo[4];
    #pragma unroll
    for (int k = 0; k < 4; ++k) {
        hi[k] = __float2bfloat16(hs[k]);
        lo[k] = __float2bfloat16(hs[k] - __bfloat162float(hi[k]));
    }
    *reinterpret_cast<uint2*>(g_hhi + coff) = *reinterpret_cast<uint2*>(hi);
    *reinterpret_cast<uint2*>(g_hlo + coff) = *reinterpret_cast<uint2*>(lo);
}

// ------------------------------ prep kernels ---------------------------------
__global__ void bias_combine(const float* __restrict__ b,
                             const float* __restrict__ bd,
                             const float* __restrict__ Wk) {
    int j = blockIdx.x * blockDim.x + threadIdx.x;
    if (j < GATES) {
        float s = b[j];
        #pragma unroll 4
        for (int k = 0; k < 256; ++k)
            s += bd[k] * Wk[(size_t)k * GATES + j];
        g_bcd[j] = s;
    } else if (j < NCOMB) {
        g_bcd[j] = bd[j - GATES];
    }
}

__global__ void copy_wd(const float* __restrict__ Wd) {
    int idx = blockIdx.x * blockDim.x + threadIdx.x;
    if (idx < UNITS * OUTU) {
        int r = idx / OUTU, c = idx % OUTU;
        g_Wcd[(size_t)r * NCOMB + GATES + c] = Wd[idx];
    }
}

// transpose + split g_Wcd[k][n] -> g_wt{hi,lo}[n][k]
__global__ void wsplit() {
    int idx = blockIdx.x * blockDim.x + threadIdx.x;   // over UNITS*NCOMB
    int k = idx / NCOMB, n = idx - k * NCOMB;
    float v = g_Wcd[idx];
    __nv_bfloat16 hi = __float2bfloat16(v);
    g_wthi[(size_t)n * UNITS + k] = hi;
    g_wtlo[(size_t)n * UNITS + k] = __float2bfloat16(v - __bfloat162float(hi));
}

// step0 weights: W0^T[n][k] : k<256 -> Wk[k][n], else Wr[k-256][n]
__global__ void w0split(const float* __restrict__ Wk, const float* __restrict__ Wr) {
    int idx = blockIdx.x * blockDim.x + threadIdx.x;   // over GATES*K0
    int n = idx & (GATES - 1);
    int k = idx >> 12;
    float v = (k < 256) ? Wk[(size_t)k * GATES + n]
                        : Wr[(size_t)(k - 256) * GATES + n];
    __nv_bfloat16 hi = __float2bfloat16(v);
    g_w0hi[(size_t)n * K0 + k] = hi;
    g_w0lo[(size_t)n * K0 + k] = __float2bfloat16(v - __bfloat162float(hi));
}

// step0 A = [x0 | h0] split
__global__ void a0split(const float* __restrict__ x0, const float* __restrict__ h0) {
    int idx = blockIdx.x * blockDim.x + threadIdx.x;
    if (idx >= BATCH * K0) return;
    int r = idx / K0, k = idx - r * K0;
    float v = (k < 256) ? x0[(size_t)r * 256 + k] : h0[(size_t)r * UNITS + (k - 256)];
    __nv_bfloat16 hi = __float2bfloat16(v);
    g_a0hi[idx] = hi;
    g_a0lo[idx] = __float2bfloat16(v - __bfloat162float(hi));
}

// ------------------------------ fp32 prep GEMM -------------------------------
__global__ __launch_bounds__(256)
void sgemm128(const float* __restrict__ A, int lda,
              const float* __restrict__ B, int ldb, int K,
              const float* __restrict__ Cadd,
              float* __restrict__ C, int ldc) {
    __shared__ float As[8][128];
    __shared__ float Bs[8][128];
    const int tid = threadIdx.x;
    const int tx = tid & 15, ty = tid >> 4;
    const int row0 = blockIdx.y * 128, col0 = blockIdx.x * 128;
    float acc[8][8];
    #pragma unroll
    for (int i = 0; i < 8; ++i)
        #pragma unroll
        for (int j = 0; j < 8; ++j) acc[i][j] = 0.0f;
    const int arow = tid >> 1, acol = (tid & 1) << 2;
    const int brow = tid >> 5, bcol = (tid & 31) << 2;
    const float* Arow = A + (size_t)(row0 + arow) * lda + acol;
    const float* Brow = B + (size_t)brow * ldb + col0 + bcol;
    for (int k0 = 0; k0 < K; k0 += 8) {
        float4 av = *reinterpret_cast<const float4*>(Arow + k0);
        float4 bv = *reinterpret_cast<const float4*>(Brow + (size_t)k0 * ldb);
        As[acol + 0][arow] = av.x; As[acol + 1][arow] = av.y;
        As[acol + 2][arow] = av.z; As[acol + 3][arow] = av.w;
        *reinterpret_cast<float4*>(&Bs[brow][bcol]) = bv;
        __syncthreads();
        #pragma unroll
        for (int k = 0; k < 8; ++k) {
            float a[8], bb[8];
            #pragma unroll
            for (int i = 0; i < 8; ++i) a[i] = As[k][ty * 8 + i];
            #pragma unroll
            for (int j = 0; j < 8; ++j) bb[j] = Bs[k][tx * 8 + j];
            #pragma unroll
            for (int i = 0; i < 8; ++i)
                #pragma unroll
                for (int j = 0; j < 8; ++j)
                    acc[i][j] = fmaf(a[i], bb[j], acc[i][j]);
        }
        __syncthreads();
    }
    const int gcol = col0 + tx * 8;
    #pragma unroll
    for (int i = 0; i < 8; ++i) {
        int r = row0 + ty * 8 + i;
        #pragma unroll
        for (int j = 0; j < 8; j += 4) {
            float4 v = make_float4(acc[i][j], acc[i][j+1], acc[i][j+2], acc[i][j+3]);
            if (Cadd) {
                float4 a4 = *reinterpret_cast<const float4*>(Cadd + (size_t)r * ldb + gcol + j);
                v.x += a4.x; v.y += a4.y; v.z += a4.z; v.w += a4.w;
            }
            *reinterpret_cast<float4*>(C + (size_t)r * ldc + gcol + j) = v;
        }
    }
}

// ------------------------------ launch ---------------------------------------
extern "C" void kernel_launch(void* const* d_in, const int* in_sizes, int n_in,
                              void* d_out, int out_size) {
    const float* x0 = (const float*)d_in[0];
    const float* h0 = (const float*)d_in[1];
    const float* c0 = (const float*)d_in[2];
    const float* Wk = (const float*)d_in[3];
    const float* Wr = (const float*)d_in[4];
    const float* b  = (const float*)d_in[5];
    const float* Wd = (const float*)d_in[6];
    const float* bd = (const float*)d_in[7];
    float* out = (float*)d_out;

    cudaFuncSetAttribute(bgemm, cudaFuncAttributeMaxDynamicSharedMemorySize, SMEM_TOTAL);

    float *pWcd, *pBcd, *pC;
    __nv_bfloat16 *pHhi, *pHlo, *pWthi, *pWtlo, *pW0hi, *pW0lo, *pA0hi, *pA0lo;
    cudaGetSymbolAddress((void**)&pWcd, g_Wcd);
    cudaGetSymbolAddress((void**)&pBcd, g_bcd);
    cudaGetSymbolAddress((void**)&pC, g_c);
    cudaGetSymbolAddress((void**)&pHhi, g_hhi);
    cudaGetSymbolAddress((void**)&pHlo, g_hlo);
    cudaGetSymbolAddress((void**)&pWthi, g_wthi);
    cudaGetSymbolAddress((void**)&pWtlo, g_wtlo);
    cudaGetSymbolAddress((void**)&pW0hi, g_w0hi);
    cudaGetSymbolAddress((void**)&pW0lo, g_w0lo);
    cudaGetSymbolAddress((void**)&pA0hi, g_a0hi);
    cudaGetSymbolAddress((void**)&pA0lo, g_a0lo);

    cudaMemcpyAsync(pC, c0, (size_t)BATCH * UNITS * sizeof(float),
                    cudaMemcpyDeviceToDevice, 0);

    // prep: combined weights/bias (fp32), then transpose + hi/lo split to bf16
    bias_combine<<<(NCOMB + 255) / 256, 256>>>(b, bd, Wk);
    copy_wd<<<(UNITS * OUTU + 255) / 256, 256>>>(Wd);
    // g_Wcd[:,0:4096] = Wd @ Wk + Wr   (M=1024, N=4096, K=256)
    sgemm128<<<dim3(GATES / 128, UNITS / 128), 256>>>(
        Wd, OUTU, Wk, GATES, 256, Wr, pWcd, NCOMB);
    wsplit<<<(UNITS * NCOMB) / 256, 256>>>();
    w0split<<<((size_t)GATES * K0) / 256, 256>>>(Wk, Wr);
    a0split<<<(BATCH * K0 + 255) / 256, 256>>>(x0, h0);

    // step 0: z0 = [x0|h0] @ W0^T + b  (32 gate tiles, K=1280)
    bgemm<<<dim3(32, 16), 256, SMEM_TOTAL>>>(
        pA0hi, pA0lo, pW0hi, pW0lo, K0, b, 0, 0, out);
    lstm_pointwise<<<(BATCH * UNITS / 4 + 255) / 256, 256>>>();

    // steps 1..95: [z_t | pred_{t-1}] = h_t @ [Wc | Wd]^T + bcd  (34 tiles, K=1024)
    for (int t = 1; t < STEPS; ++t) {
        bgemm<<<dim3(34, 16), 256, SMEM_TOTAL>>>(
            pHhi, pHlo, pWthi, pWtlo, UNITS, pBcd, 0, t, out);
        lstm_pointwise<<<(BATCH * UNITS / 4 + 255) / 256, 256>>>();
    }

    // final: pred_95 = h_96 @ Wd^T + bd  (pred tiles only)
    bgemm<<<dim3(2, 16), 256, SMEM_TOTAL>>>(
        pHhi, pHlo, pWthi, pWtlo, UNITS, pBcd, 32, STEPS, out);
}

// round 4
// speedup vs baseline: 2.5229x; 1.4127x over previous
#include <cuda_runtime.h>
#include <cuda_fp16.h>
#include <cstdint>
#include <math.h>

#define BATCH 2048
#define UNITS 1024
#define GATES 4096
#define OUTU 256
#define NCOMB 4352            // [Wc | Wd]
#define STEPS 96
#define K0 1280               // step-0 K: [x | h]
#define LDO (STEPS * OUTU)
#define LOSCALE 2048.0f
#define INV_LOSCALE (1.0f / 2048.0f)

// ------------------------------ device scratch ------------------------------
__device__ __align__(256) float g_Wcd[UNITS * NCOMB];   // fp32 combined weights (non-interleaved)
__device__ __align__(256) float g_bcd[NCOMB];           // combined bias (gate-interleaved + pred)
__device__ __align__(256) float g_b0i[GATES];           // step0 bias b (gate-interleaved)
__device__ __align__(256) float g_c[BATCH * UNITS];     // cell state fp32
__device__ __align__(256) __half g_h0hi[BATCH * UNITS]; // h ping-pong buffers (fp16 hi/lo*2048)
__device__ __align__(256) __half g_h0lo[BATCH * UNITS];
__device__ __align__(256) __half g_h1hi[BATCH * UNITS];
__device__ __align__(256) __half g_h1lo[BATCH * UNITS];
__device__ __align__(256) __half g_wthi[(size_t)NCOMB * UNITS];  // W^T split, interleaved rows
__device__ __align__(256) __half g_wtlo[(size_t)NCOMB * UNITS];
__device__ __align__(256) __half g_w0hi[(size_t)GATES * K0];     // step0 W^T, interleaved rows
__device__ __align__(256) __half g_w0lo[(size_t)GATES * K0];
__device__ __align__(256) __half g_a0hi[(size_t)BATCH * K0];     // step0 A=[x|h]
__device__ __align__(256) __half g_a0lo[(size_t)BATCH * K0];

__device__ __forceinline__ int icol(int n) {            // gate interleave: unit*4+gate
    return (n < GATES) ? ((n & 1023) * 4 + (n >> 10)) : n;
}

// ------------------------------ PTX helpers ---------------------------------
__device__ __forceinline__ uint32_t smem_u32(const void* p) {
    uint32_t a;
    asm("{ .reg .u64 t; cvta.to.shared.u64 t, %1; cvt.u32.u64 %0, t; }" : "=r"(a) : "l"(p));
    return a;
}
__device__ __forceinline__ uint32_t swz(uint32_t off) { return off ^ ((off >> 3) & 0x70); }
__device__ __forceinline__ void cpa16(uint32_t dst, const void* src) {
    asm volatile("cp.async.cg.shared.global [%0], [%1], 16;" :: "r"(dst), "l"(src) : "memory");
}
#define CP_COMMIT()  asm volatile("cp.async.commit_group;" ::: "memory")
#define CP_WAIT(n)   asm volatile("cp.async.wait_group %0;" :: "n"(n) : "memory")

__device__ __forceinline__ void ldsm4(uint32_t* r, uint32_t addr) {
    asm volatile("ldmatrix.sync.aligned.m8n8.x4.shared.b16 {%0,%1,%2,%3}, [%4];"
        : "=r"(r[0]), "=r"(r[1]), "=r"(r[2]), "=r"(r[3]) : "r"(addr));
}
// main: fp16 in, fp32 acc
__device__ __forceinline__ void mma_f32(float* d, const uint32_t* a, uint32_t b0, uint32_t b1) {
    asm volatile("mma.sync.aligned.m16n8k16.row.col.f32.f16.f16.f32 "
        "{%0,%1,%2,%3}, {%4,%5,%6,%7}, {%8,%9}, {%0,%1,%2,%3};"
        : "+f"(d[0]), "+f"(d[1]), "+f"(d[2]), "+f"(d[3])
        : "r"(a[0]), "r"(a[1]), "r"(a[2]), "r"(a[3]), "r"(b0), "r"(b1));
}
// correction: fp16 in, fp16 acc (2x rate)
__device__ __forceinline__ void mma_f16(uint32_t* d, const uint32_t* a, uint32_t b0, uint32_t b1) {
    asm volatile("mma.sync.aligned.m16n8k16.row.col.f16.f16.f16.f16 "
        "{%0,%1}, {%2,%3,%4,%5}, {%6,%7}, {%0,%1};"
        : "+r"(d[0]), "+r"(d[1])
        : "r"(a[0]), "r"(a[1]), "r"(a[2]), "r"(a[3]), "r"(b0), "r"(b1));
}

// ------------------------------ fused split-GEMM + LSTM ----------------------
// C[2048 x Ncols] = A[2048 x K] @ B^T, all operands fp16 hi + (lo*2048).
// acc = hi*hi (fp32) + (hi*lo' + lo'*hi) (fp16 acc) / 2048.
// Block tile 128x128, 512 thr (4x4 warps, 32x32 each), KC=64, 3-stage cp.async.
// Gate tiles (interleaved cols): fused LSTM pointwise epilogue, writes c + h'.
// Pred tiles (cols >= GATES): writes preds into d_out.
#define KC 64
#define OFF_AHI 0
#define OFF_ALO 16384
#define OFF_BHI 32768
#define OFF_BLO 49152
#define STAGE_BYTES 65536
#define SMEM_TOTAL (3 * STAGE_BYTES)

__device__ __forceinline__ void load_chunk(
    uint32_t sb, int tid,
    const __half* __restrict__ ahi, const __half* __restrict__ alo,
    const __half* __restrict__ bhi, const __half* __restrict__ blo,
    int r0, int n0, int K, int kc)
{
    const int kcol = kc * KC;
    #pragma unroll
    for (int i = 0; i < 2; ++i) {
        int q = tid + i * 512;
        int row = q >> 3, jj = q & 7;              // 128 rows x 8 chunks of 16B
        uint32_t so = swz(row * 128 + jj * 16);
        size_t ga = (size_t)(r0 + row) * K + kcol + jj * 8;
        size_t gb = (size_t)(n0 + row) * K + kcol + jj * 8;
        cpa16(sb + OFF_AHI + so, ahi + ga);
        cpa16(sb + OFF_ALO + so, alo + ga);
        cpa16(sb + OFF_BHI + so, bhi + gb);
        cpa16(sb + OFF_BLO + so, blo + gb);
    }
    CP_COMMIT();
}

__global__ __launch_bounds__(512, 1)
void bgemm(const __half* __restrict__ ahi, const __half* __restrict__ alo,
           const __half* __restrict__ bhi, const __half* __restrict__ blo,
           int K, const float* __restrict__ bias, int n_tile_off, int t,
           float* __restrict__ outp,
           __half* __restrict__ hout_hi, __half* __restrict__ hout_lo)
{
    extern __shared__ __align__(1024) char smem[];
    const uint32_t sbase = smem_u32(smem);
    const int tid = threadIdx.x;
    const int lane = tid & 31, w = tid >> 5;
    const int wm = w & 3, wn = w >> 2;             // 4 (m) x 4 (n) warps
    const int r0 = blockIdx.y * 128;
    const int n0 = (blockIdx.x + n_tile_off) * 128;
    const int nch = K / KC;

    float dm[2][4][4];
    uint32_t dc[2][4][2];
    #pragma unroll
    for (int mi = 0; mi < 2; ++mi)
        #pragma unroll
        for (int nj = 0; nj < 4; ++nj) {
            #pragma unroll
            for (int q = 0; q < 4; ++q) dm[mi][nj][q] = 0.0f;
            dc[mi][nj][0] = 0u; dc[mi][nj][1] = 0u;
        }

    load_chunk(sbase + 0 * STAGE_BYTES, tid, ahi, alo, bhi, blo, r0, n0, K, 0);
    load_chunk(sbase + 1 * STAGE_BYTES, tid, ahi, alo, bhi, blo, r0, n0, K, 1);

    const int lr = lane & 7, sel = lane >> 3;

    for (int kc = 0; kc < nch; ++kc) {
        if (kc + 2 < nch) {
            load_chunk(sbase + ((kc + 2) % 3) * STAGE_BYTES, tid,
                       ahi, alo, bhi, blo, r0, n0, K, kc + 2);
            CP_WAIT(2);
        } else if (kc + 1 < nch) {
            CP_WAIT(1);
        } else {
            CP_WAIT(0);
        }
        __syncthreads();
        const uint32_t sb = sbase + (kc % 3) * STAGE_BYTES;

        #pragma unroll
        for (int k16 = 0; k16 < 4; ++k16) {
            uint32_t ah[2][4], al[2][4];
            #pragma unroll
            for (int mi = 0; mi < 2; ++mi) {
                int row = wm * 32 + mi * 16 + lr + (sel & 1) * 8;
                int kb = (k16 * 16 + (sel >> 1) * 8) * 2;
                uint32_t off = swz(row * 128 + kb);
                ldsm4(ah[mi], sb + OFF_AHI + off);
                ldsm4(al[mi], sb + OFF_ALO + off);
            }
            uint32_t bh[2][4], bl[2][4];
            #pragma unroll
            for (int njp = 0; njp < 2; ++njp) {
                int nrow = wn * 32 + njp * 16 + lr + (sel >> 1) * 8;
                int kb = (k16 * 16 + (sel & 1) * 8) * 2;
                uint32_t off = swz(nrow * 128 + kb);
                ldsm4(bh[njp], sb + OFF_BHI + off);
                ldsm4(bl[njp], sb + OFF_BLO + off);
            }
            // product-outer ordering: no back-to-back same-accumulator MMAs
            #pragma unroll
            for (int mi = 0; mi < 2; ++mi)
                #pragma unroll
                for (int nj = 0; nj < 4; ++nj)
                    mma_f32(dm[mi][nj], ah[mi],
                            bh[nj >> 1][(nj & 1) * 2], bh[nj >> 1][(nj & 1) * 2 + 1]);
            #pragma unroll
            for (int mi = 0; mi < 2; ++mi)
                #pragma unroll
                for (int nj = 0; nj < 4; ++nj)
                    mma_f16(dc[mi][nj], ah[mi],
                            bl[nj >> 1][(nj & 1) * 2], bl[nj >> 1][(nj & 1) * 2 + 1]);
            #pragma unroll
            for (int mi = 0; mi < 2; ++mi)
                #pragma unroll
                for (int nj = 0; nj < 4; ++nj)
                    mma_f16(dc[mi][nj], al[mi],
                            bh[nj >> 1][(nj & 1) * 2], bh[nj >> 1][(nj & 1) * 2 + 1]);
        }
        __syncthreads();
    }

    // ---------------- epilogue ----------------
    const bool isPred = (n0 >= GATES);
    const int qr = lane >> 2, t4 = lane & 3, qc = t4 * 2;

    #pragma unroll
    for (int mi = 0; mi < 2; ++mi) {
        #pragma unroll
        for (int half = 0; half < 2; ++half) {
            const int r = r0 + wm * 32 + mi * 16 + qr + half * 8;
            #pragma unroll
            for (int nj = 0; nj < 4; ++nj) {
                const int c = wn * 32 + nj * 8 + qc;
                __half2 hc = *reinterpret_cast<__half2*>(&dc[mi][nj][half]);
                float zx = dm[mi][nj][half * 2 + 0]
                         + INV_LOSCALE * __half2float(__low2half(hc)) + bias[n0 + c];
                float zy = dm[mi][nj][half * 2 + 1]
                         + INV_LOSCALE * __half2float(__high2half(hc)) + bias[n0 + c + 1];
                if (isPred) {
                    float2 v = make_float2(zx, zy);
                    *reinterpret_cast<float2*>(
                        outp + (size_t)r * LDO + (size_t)(t - 1) * OUTU + (n0 - GATES) + c) = v;
                } else {
                    // gate-interleaved: even t4 holds (zi,zf), odd holds (zg,zo) of unit u
                    float ox = __shfl_xor_sync(0xffffffffu, zx, 1);
                    float oy = __shfl_xor_sync(0xffffffffu, zy, 1);
                    if ((t4 & 1) == 0) {
                        const int u = ((n0 + c) >> 2);
                        const size_t off = (size_t)r * UNITS + u;
                        float ig = 1.0f / (1.0f + expf(-zx));
                        float fg = 1.0f / (1.0f + expf(-zy));
                        float gg = tanhf(ox);
                        float og = 1.0f / (1.0f + expf(-oy));
                        float cn = fg * g_c[off] + ig * gg;
                        g_c[off] = cn;
                        float h = og * tanhf(cn);
                        __half hh = __float2half_rn(h);
                        hout_hi[off] = hh;
                        hout_lo[off] = __float2half_rn((h - __half2float(hh)) * LOSCALE);
                    }
                }
            }
        }
    }
}

// ------------------------------ prep kernels ---------------------------------
__global__ void bias_combine(const float* __restrict__ b,
                             const float* __restrict__ bd,
                             const float* __restrict__ Wk) {
    int j = blockIdx.x * blockDim.x + threadIdx.x;
    if (j < GATES) {
        float s = b[j];
        #pragma unroll 4
        for (int k = 0; k < 256; ++k)
            s += bd[k] * Wk[(size_t)k * GATES + j];
        g_bcd[icol(j)] = s;
        g_b0i[icol(j)] = b[j];
    } else if (j < NCOMB) {
        g_bcd[j] = bd[j - GATES];
    }
}

__global__ void copy_wd(const float* __restrict__ Wd) {
    int idx = blockIdx.x * blockDim.x + threadIdx.x;
    if (idx < UNITS * OUTU) {
        int r = idx / OUTU, c = idx % OUTU;
        g_Wcd[(size_t)r * NCOMB + GATES + c] = Wd[idx];
    }
}

// transpose + interleave + fp16 split: g_Wcd[k][n] -> g_wt{hi,lo}[icol(n)][k]
__global__ void wsplit() {
    int idx = blockIdx.x * blockDim.x + threadIdx.x;   // over UNITS*NCOMB
    int k = idx / NCOMB, n = idx - k * NCOMB;
    float v = g_Wcd[idx];
    __half hi = __float2half_rn(v);
    size_t o = (size_t)icol(n) * UNITS + k;
    g_wthi[o] = hi;
    g_wtlo[o] = __float2half_rn((v - __half2float(hi)) * LOSCALE);
}

// step0 weights: W0^T[icol(n)][k] : k<256 -> Wk[k][n], else Wr[k-256][n]
__global__ void w0split(const float* __restrict__ Wk, const float* __restrict__ Wr) {
    int idx = blockIdx.x * blockDim.x + threadIdx.x;   // over GATES*K0
    int n = idx & (GATES - 1);
    int k = idx >> 12;
    float v = (k < 256) ? Wk[(size_t)k * GATES + n]
                        : Wr[(size_t)(k - 256) * GATES + n];
    __half hi = __float2half_rn(v);
    size_t o = (size_t)icol(n) * K0 + k;
    g_w0hi[o] = hi;
    g_w0lo[o] = __float2half_rn((v - __half2float(hi)) * LOSCALE);
}

// step0 A = [x0 | h0] fp16 split
__global__ void a0split(const float* __restrict__ x0, const float* __restrict__ h0) {
    int idx = blockIdx.x * blockDim.x + threadIdx.x;
    if (idx >= BATCH * K0) return;
    int r = idx / K0, k = idx - r * K0;
    float v = (k < 256) ? x0[(size_t)r * 256 + k] : h0[(size_t)r * UNITS + (k - 256)];
    __half hi = __float2half_rn(v);
    g_a0hi[idx] = hi;
    g_a0lo[idx] = __float2half_rn((v - __half2float(hi)) * LOSCALE);
}

// ------------------------------ fp32 prep GEMM -------------------------------
__global__ __launch_bounds__(256)
void sgemm128(const float* __restrict__ A, int lda,
              const float* __restrict__ B, int ldb, int K,
              const float* __restrict__ Cadd,
              float* __restrict__ C, int ldc) {
    __shared__ float As[8][128];
    __shared__ float Bs[8][128];
    const int tid = threadIdx.x;
    const int tx = tid & 15, ty = tid >> 4;
    const int row0 = blockIdx.y * 128, col0 = blockIdx.x * 128;
    float acc[8][8];
    #pragma unroll
    for (int i = 0; i < 8; ++i)
        #pragma unroll
        for (int j = 0; j < 8; ++j) acc[i][j] = 0.0f;
    const int arow = tid >> 1, acol = (tid & 1) << 2;
    const int brow = tid >> 5, bcol = (tid & 31) << 2;
    const float* Arow = A + (size_t)(row0 + arow) * lda + acol;
    const float* Brow = B + (size_t)brow * ldb + col0 + bcol;
    for (int k0 = 0; k0 < K; k0 += 8) {
        float4 av = *reinterpret_cast<const float4*>(Arow + k0);
        float4 bv = *reinterpret_cast<const float4*>(Brow + (size_t)k0 * ldb);
        As[acol + 0][arow] = av.x; As[acol + 1][arow] = av.y;
        As[acol + 2][arow] = av.z; As[acol + 3][arow] = av.w;
        *reinterpret_cast<float4*>(&Bs[brow][bcol]) = bv;
        __syncthreads();
        #pragma unroll
        for (int k = 0; k < 8; ++k) {
            float a[8], bb[8];
            #pragma unroll
            for (int i = 0; i < 8; ++i) a[i] = As[k][ty * 8 + i];
            #pragma unroll
            for (int j = 0; j < 8; ++j) bb[j] = Bs[k][tx * 8 + j];
            #pragma unroll
            for (int i = 0; i < 8; ++i)
                #pragma unroll
                for (int j = 0; j < 8; ++j)
                    acc[i][j] = fmaf(a[i], bb[j], acc[i][j]);
        }
        __syncthreads();
    }
    const int gcol = col0 + tx * 8;
    #pragma unroll
    for (int i = 0; i < 8; ++i) {
        int r = row0 + ty * 8 + i;
        #pragma unroll
        for (int j = 0; j < 8; j += 4) {
            float4 v = make_float4(acc[i][j], acc[i][j+1], acc[i][j+2], acc[i][j+3]);
            if (Cadd) {
                float4 a4 = *reinterpret_cast<const float4*>(Cadd + (size_t)r * ldb + gcol + j);
                v.x += a4.x; v.y += a4.y; v.z += a4.z; v.w += a4.w;
            }
            *reinterpret_cast<float4*>(C + (size_t)r * ldc + gcol + j) = v;
        }
    }
}

// ------------------------------ launch ---------------------------------------
extern "C" void kernel_launch(void* const* d_in, const int* in_sizes, int n_in,
                              void* d_out, int out_size) {
    const float* x0 = (const float*)d_in[0];
    const float* h0 = (const float*)d_in[1];
    const float* c0 = (const float*)d_in[2];
    const float* Wk = (const float*)d_in[3];
    const float* Wr = (const float*)d_in[4];
    const float* b  = (const float*)d_in[5];
    const float* Wd = (const float*)d_in[6];
    const float* bd = (const float*)d_in[7];
    float* out = (float*)d_out;

    cudaFuncSetAttribute(bgemm, cudaFuncAttributeMaxDynamicSharedMemorySize, SMEM_TOTAL);

    float *pWcd, *pBcd, *pB0i, *pC;
    __half *pWthi, *pWtlo, *pW0hi, *pW0lo, *pA0hi, *pA0lo;
    __half *pH0hi, *pH0lo, *pH1hi, *pH1lo;
    cudaGetSymbolAddress((void**)&pWcd, g_Wcd);
    cudaGetSymbolAddress((void**)&pBcd, g_bcd);
    cudaGetSymbolAddress((void**)&pB0i, g_b0i);
    cudaGetSymbolAddress((void**)&pC, g_c);
    cudaGetSymbolAddress((void**)&pWthi, g_wthi);
    cudaGetSymbolAddress((void**)&pWtlo, g_wtlo);
    cudaGetSymbolAddress((void**)&pW0hi, g_w0hi);
    cudaGetSymbolAddress((void**)&pW0lo, g_w0lo);
    cudaGetSymbolAddress((void**)&pA0hi, g_a0hi);
    cudaGetSymbolAddress((void**)&pA0lo, g_a0lo);
    cudaGetSymbolAddress((void**)&pH0hi, g_h0hi);
    cudaGetSymbolAddress((void**)&pH0lo, g_h0lo);
    cudaGetSymbolAddress((void**)&pH1hi, g_h1hi);
    cudaGetSymbolAddress((void**)&pH1lo, g_h1lo);

    cudaMemcpyAsync(pC, c0, (size_t)BATCH * UNITS * sizeof(float),
                    cudaMemcpyDeviceToDevice, 0);

    // prep
    bias_combine<<<(NCOMB + 255) / 256, 256>>>(b, bd, Wk);
    copy_wd<<<(UNITS * OUTU + 255) / 256, 256>>>(Wd);
    sgemm128<<<dim3(GATES / 128, UNITS / 128), 256>>>(
        Wd, OUTU, Wk, GATES, 256, Wr, pWcd, NCOMB);      // Wc = Wd@Wk + Wr
    wsplit<<<(UNITS * NCOMB) / 256, 256>>>();
    w0split<<<((size_t)GATES * K0) / 256, 256>>>(Wk, Wr);
    a0split<<<(BATCH * K0 + 255) / 256, 256>>>(x0, h0);

    // h buffers: step t reads hb[t&1], writes hb[(t+1)&1]; step0 writes hb[1]
    __half* hhi[2] = {pH0hi, pH1hi};
    __half* hlo[2] = {pH0lo, pH1lo};

    // step 0: gates only (32 tiles), K=1280, fused LSTM -> h1
    bgemm<<<dim3(32, 16), 512, SMEM_TOTAL>>>(
        pA0hi, pA0lo, pW0hi, pW0lo, K0, pB0i, 0, 0, out, hhi[1], hlo[1]);

    // steps 1..95: gates + pred_{t-1} (34 tiles), K=1024
    for (int t = 1; t < STEPS; ++t) {
        bgemm<<<dim3(34, 16), 512, SMEM_TOTAL>>>(
            hhi[t & 1], hlo[t & 1], pWthi, pWtlo, UNITS, pBcd, 0, t, out,
            hhi[(t + 1) & 1], hlo[(t + 1) & 1]);
    }

    // final: pred_95 only (2 pred tiles), reads h_96 = hb[0]
    bgemm<<<dim3(2, 16), 512, SMEM_TOTAL>>>(
        hhi[0], hlo[0], pWthi, pWtlo, UNITS, pBcd, 32, STEPS, out,
        hhi[1], hlo[1]);
}